// round 5
// baseline (speedup 1.0000x reference)
#include <cuda_runtime.h>

// Problem constants (shapes fixed by dataset; code stays correct for any
// batch_list via the offsets kernel + generic path).
#define D_DIM   300          // embedding dim
#define DC      60           // columns per chunk (multiple of 4, divides 300)
#define DC4     (DC / 4)     // 15 float4 per row-chunk
#define NCHUNK  (D_DIM / DC) // 5
#define TR      256          // row tile (== nodes per graph in this dataset)
#define RB      32           // row-blocks
#define NT      (RB * DC4)   // 480 threads per CTA
#define KIT     (TR / RB)    // 8 rows per thread in fast path
#define MAXB    8192
#define EPSV    1e-12f

// Scratch (no cudaMalloc allowed): per-graph row offsets + actual graph count.
__device__ int g_off[MAXB + 1];
__device__ int g_B;

// ---------------------------------------------------------------------------
// Offsets kernel: detects int32 vs int64 batch_list layout. Fast path: if all
// counts are equal (dataset case), writes offsets arithmetically with no scan.
// Fallback: block-wide inclusive scan.
// ---------------------------------------------------------------------------
__global__ void offsets_kernel(const int* __restrict__ p32, int nb, int ntot) {
    __shared__ int sh[1024];
    __shared__ int s_stride, s_carry, s_uni, s_val;
    const int tid = threadIdx.x;

    if (tid == 0) {
        int stride = 1;
        if (nb > 1) {
            int v0 = p32[0], v1 = p32[1];
            if (v1 == 0 && v0 != 0) stride = 2;   // int64 little-endian
        }
        s_stride = stride;
        s_carry = 0;
        s_uni = 1;
        s_val = p32[0];
        g_off[0] = 0;
    }
    __syncthreads();

    const int st = s_stride;
    int B = nb;
    if (B > MAXB) B = MAXB;
    const int B1 = (st == 2) ? (B >> 1) : B;
    const int v0 = s_val;

    int uni = 1;
    for (int i = tid; i < B1; i += 1024)
        if (p32[(size_t)i * st] != v0) uni = 0;
    if (!uni) atomicAnd(&s_uni, 0);
    __syncthreads();

    if (s_uni && (long long)B1 * v0 == ntot) {
        for (int i = tid; i < B1; i += 1024)
            g_off[i + 1] = (i + 1) * v0;
        if (tid == 0) g_B = B1;
        return;
    }

    for (int base = 0; base < B1; base += 1024) {
        int i = base + tid;
        int v = (i < B1) ? p32[(size_t)i * st] : 0;
        sh[tid] = v;
        __syncthreads();
        #pragma unroll
        for (int o = 1; o < 1024; o <<= 1) {
            int t = (tid >= o) ? sh[tid - o] : 0;
            __syncthreads();
            sh[tid] += t;
            __syncthreads();
        }
        if (i < B1) g_off[i + 1] = s_carry + sh[tid];
        __syncthreads();
        if (tid == 0) s_carry += sh[1023];
        __syncthreads();
    }

    int Bfinal = B1;
    if (st == 2 && B1 > 0 && g_off[B1] != ntot && B > B1) {
        for (int base = B1; base < B; base += 1024) {
            int i = base + tid;
            int v = (i < B) ? p32[(size_t)i * st] : 0;
            sh[tid] = v;
            __syncthreads();
            #pragma unroll
            for (int o = 1; o < 1024; o <<= 1) {
                int t = (tid >= o) ? sh[tid - o] : 0;
                __syncthreads();
                sh[tid] += t;
                __syncthreads();
            }
            if (i < B) g_off[i + 1] = s_carry + sh[tid];
            __syncthreads();
            if (tid == 0) s_carry += sh[1023];
            __syncthreads();
        }
        Bfinal = B;
    }
    if (tid == 0) g_B = Bfinal;
}

// ---------------------------------------------------------------------------
// Helpers
// ---------------------------------------------------------------------------
__device__ __forceinline__ float4 min4(float4 a, float4 b) {
    return make_float4(fminf(a.x, b.x), fminf(a.y, b.y),
                       fminf(a.z, b.z), fminf(a.w, b.w));
}
__device__ __forceinline__ float4 max4(float4 a, float4 b) {
    return make_float4(fmaxf(a.x, b.x), fmaxf(a.y, b.y),
                       fmaxf(a.z, b.z), fmaxf(a.w, b.w));
}

// ---------------------------------------------------------------------------
// Main kernel: one CTA per (graph, 60-column chunk).
// Fast path: stream tile gmem->regs->smem while reducing min/max in registers
// (tile is WRITTEN to smem once and READ once; no separate reduce sweep).
// Fold 32x15 float4 partials with 2 combine stages, publish mid/inv, then
// normalize from the smem tile and stream out. 3 CTAs/SM, ~70% occupancy;
// single DRAM read + single DRAM write.
// ---------------------------------------------------------------------------
__global__ void __launch_bounds__(NT, 3)
cube_norm_kernel(const float* __restrict__ x, float* __restrict__ y) {
    extern __shared__ float4 sm4[];
    float4* tile4 = sm4;                       // KIT*NT = 3840 float4 (61440 B)
    float4* pmn   = sm4 + KIT * NT;            // 16*15 = 240 float4 (3840 B)
    float4* pmx   = pmn + (RB / 2) * DC4;      // 240 float4 (3840 B)
    float4* s_mid = pmx + (RB / 2) * DC4;      // 15 float4
    float4* s_inv = s_mid + DC4;               // 15 float4

    const int g = blockIdx.y;
    if (g >= g_B) return;
    const int c0 = blockIdx.x * DC;
    const int r0 = g_off[g];
    const int nr = g_off[g + 1] - r0;
    if (nr <= 0) return;

    const int tid = threadIdx.x;
    const int j   = tid % DC4;         // column quad 0..14
    const int rb  = tid / DC4;         // row block 0..31

    const float* xg = x + (size_t)r0 * D_DIM + c0 + 4 * j;
    float*       yg = y + (size_t)r0 * D_DIM + c0 + 4 * j;
    const float* p  = xg + (size_t)rb * D_DIM;
    float*       q  = yg + (size_t)rb * D_DIM;

    if (nr == TR) {
        // ---- pass 1: gmem -> regs -> smem tile, reduce in flight ----
        float4 mn, mx;
        {
            float4 v = __ldcs((const float4*)p);
            tile4[tid] = v;
            mn = v; mx = v;
        }
        #pragma unroll
        for (int k = 1; k < KIT; k++) {
            float4 v = __ldcs((const float4*)(p + (size_t)k * RB * D_DIM));
            tile4[k * NT + tid] = v;
            mn = min4(mn, v);
            mx = max4(mx, v);
        }

        // ---- fold: 32 -> 16 (register combine) -> 1 ----
        if (rb < RB / 2) {
            pmn[rb * DC4 + j] = mn;
            pmx[rb * DC4 + j] = mx;
        }
        __syncthreads();
        if (rb >= RB / 2) {
            int r = (rb - RB / 2) * DC4 + j;
            pmn[r] = min4(pmn[r], mn);
            pmx[r] = max4(pmx[r], mx);
        }
        __syncthreads();
        if (tid < DC4) {
            float4 fmn = pmn[tid];
            float4 fmx = pmx[tid];
            #pragma unroll
            for (int r = 1; r < RB / 2; r++) {
                fmn = min4(fmn, pmn[r * DC4 + tid]);
                fmx = max4(fmx, pmx[r * DC4 + tid]);
            }
            float4 mid = make_float4((fmx.x + fmn.x) * 0.5f,
                                     (fmx.y + fmn.y) * 0.5f,
                                     (fmx.z + fmn.z) * 0.5f,
                                     (fmx.w + fmn.w) * 0.5f);
            float4 inv = make_float4(
                1.0f / fmaxf((fmx.x - fmn.x) * 0.5f, EPSV),
                1.0f / fmaxf((fmx.y - fmn.y) * 0.5f, EPSV),
                1.0f / fmaxf((fmx.z - fmn.z) * 0.5f, EPSV),
                1.0f / fmaxf((fmx.w - fmn.w) * 0.5f, EPSV));
            s_mid[tid] = mid;
            s_inv[tid] = inv;
        }
        __syncthreads();

        const float4 mid = s_mid[j];
        const float4 inv = s_inv[j];

        // ---- pass 2: smem tile -> normalize -> stream out ----
        #pragma unroll
        for (int k = 0; k < KIT; k++) {
            float4 a = tile4[k * NT + tid];
            float4 o;
            o.x = (a.x - mid.x) * inv.x;
            o.y = (a.y - mid.y) * inv.y;
            o.z = (a.z - mid.z) * inv.z;
            o.w = (a.w - mid.w) * inv.w;
            __stcs((float4*)(q + (size_t)k * RB * D_DIM), o);
        }
    } else {
        // ---------------- generic two-sweep path (not hit by dataset) ------
        float4 mn = make_float4( 3.402823466e38f,  3.402823466e38f,
                                 3.402823466e38f,  3.402823466e38f);
        float4 mx = make_float4(-3.402823466e38f, -3.402823466e38f,
                                -3.402823466e38f, -3.402823466e38f);
        for (int r = rb; r < nr; r += RB) {
            float4 a = *(const float4*)(xg + (size_t)r * D_DIM);
            mn = min4(mn, a);
            mx = max4(mx, a);
        }
        if (rb < RB / 2) {
            pmn[rb * DC4 + j] = mn;
            pmx[rb * DC4 + j] = mx;
        }
        __syncthreads();
        if (rb >= RB / 2) {
            int r = (rb - RB / 2) * DC4 + j;
            pmn[r] = min4(pmn[r], mn);
            pmx[r] = max4(pmx[r], mx);
        }
        __syncthreads();
        if (tid < DC4) {
            float4 fmn = pmn[tid];
            float4 fmx = pmx[tid];
            #pragma unroll
            for (int r = 1; r < RB / 2; r++) {
                fmn = min4(fmn, pmn[r * DC4 + tid]);
                fmx = max4(fmx, pmx[r * DC4 + tid]);
            }
            float4 mid = make_float4((fmx.x + fmn.x) * 0.5f,
                                     (fmx.y + fmn.y) * 0.5f,
                                     (fmx.z + fmn.z) * 0.5f,
                                     (fmx.w + fmn.w) * 0.5f);
            float4 inv = make_float4(
                1.0f / fmaxf((fmx.x - fmn.x) * 0.5f, EPSV),
                1.0f / fmaxf((fmx.y - fmn.y) * 0.5f, EPSV),
                1.0f / fmaxf((fmx.z - fmn.z) * 0.5f, EPSV),
                1.0f / fmaxf((fmx.w - fmn.w) * 0.5f, EPSV));
            s_mid[tid] = mid;
            s_inv[tid] = inv;
        }
        __syncthreads();
        const float4 mid = s_mid[j];
        const float4 inv = s_inv[j];
        for (int r = rb; r < nr; r += RB) {
            float4 a = *(const float4*)(xg + (size_t)r * D_DIM);
            float4 o;
            o.x = (a.x - mid.x) * inv.x;
            o.y = (a.y - mid.y) * inv.y;
            o.z = (a.z - mid.z) * inv.z;
            o.w = (a.w - mid.w) * inv.w;
            *(float4*)(yg + (size_t)r * D_DIM) = o;
        }
    }
}

// ---------------------------------------------------------------------------
extern "C" void kernel_launch(void* const* d_in, const int* in_sizes, int n_in,
                              void* d_out, int out_size) {
    const float* x  = (const float*)d_in[0];
    const int*   bl = (const int*)d_in[1];
    float*       y  = (float*)d_out;

    const int nb   = in_sizes[1];
    const int ntot = in_sizes[0] / D_DIM;

    // tile + 2*(16*15) partials + 2*15 stats, in float4 units
    const int smem = (KIT * NT + 2 * (RB / 2) * DC4 + 2 * DC4) * 16; // 69,600 B
    cudaFuncSetAttribute(cube_norm_kernel,
                         cudaFuncAttributeMaxDynamicSharedMemorySize, smem);

    offsets_kernel<<<1, 1024>>>(bl, nb, ntot);

    int gy = nb < MAXB ? nb : MAXB;
    if (gy < 1) gy = 1;
    dim3 grid(NCHUNK, gy);
    cube_norm_kernel<<<grid, NT, smem>>>(x, y);
}

// round 6
// speedup vs baseline: 1.4941x; 1.4941x over previous
#include <cuda_runtime.h>

// Problem constants (shapes fixed by dataset; code stays correct for any
// batch_list via the offsets kernel + generic path).
#define D_DIM   300          // embedding dim
#define DC      60           // columns per chunk (multiple of 4, divides 300)
#define DC4     (DC / 4)     // 15 float4 per row-chunk
#define NCHUNK  (D_DIM / DC) // 5
#define TR      256          // row tile (== nodes per graph in this dataset)
#define RB      32           // row-blocks
#define NT      (RB * DC4)   // 480 threads per CTA
#define KIT     (TR / RB)    // 8 rows per thread in fast path
#define MAXB    8192
#define EPSV    1e-12f

// Scratch (no cudaMalloc allowed): per-graph row offsets + actual graph count.
__device__ int g_off[MAXB + 1];
__device__ int g_B;

// ---------------------------------------------------------------------------
// Offsets kernel: detects int32 vs int64 batch_list layout. Fast path: if all
// counts are equal (dataset case), writes offsets arithmetically with no scan.
// Fallback: block-wide inclusive scan.
// ---------------------------------------------------------------------------
__global__ void offsets_kernel(const int* __restrict__ p32, int nb, int ntot) {
    __shared__ int sh[1024];
    __shared__ int s_stride, s_carry, s_uni, s_val;
    const int tid = threadIdx.x;

    if (tid == 0) {
        int stride = 1;
        if (nb > 1) {
            int v0 = p32[0], v1 = p32[1];
            if (v1 == 0 && v0 != 0) stride = 2;   // int64 little-endian
        }
        s_stride = stride;
        s_carry = 0;
        s_uni = 1;
        s_val = p32[0];
        g_off[0] = 0;
    }
    __syncthreads();

    const int st = s_stride;
    int B = nb;
    if (B > MAXB) B = MAXB;
    const int B1 = (st == 2) ? (B >> 1) : B;
    const int v0 = s_val;

    int uni = 1;
    for (int i = tid; i < B1; i += 1024)
        if (p32[(size_t)i * st] != v0) uni = 0;
    if (!uni) atomicAnd(&s_uni, 0);
    __syncthreads();

    if (s_uni && (long long)B1 * v0 == ntot) {
        for (int i = tid; i < B1; i += 1024)
            g_off[i + 1] = (i + 1) * v0;
        if (tid == 0) g_B = B1;
        return;
    }

    for (int base = 0; base < B1; base += 1024) {
        int i = base + tid;
        int v = (i < B1) ? p32[(size_t)i * st] : 0;
        sh[tid] = v;
        __syncthreads();
        #pragma unroll
        for (int o = 1; o < 1024; o <<= 1) {
            int t = (tid >= o) ? sh[tid - o] : 0;
            __syncthreads();
            sh[tid] += t;
            __syncthreads();
        }
        if (i < B1) g_off[i + 1] = s_carry + sh[tid];
        __syncthreads();
        if (tid == 0) s_carry += sh[1023];
        __syncthreads();
    }

    int Bfinal = B1;
    if (st == 2 && B1 > 0 && g_off[B1] != ntot && B > B1) {
        for (int base = B1; base < B; base += 1024) {
            int i = base + tid;
            int v = (i < B) ? p32[(size_t)i * st] : 0;
            sh[tid] = v;
            __syncthreads();
            #pragma unroll
            for (int o = 1; o < 1024; o <<= 1) {
                int t = (tid >= o) ? sh[tid - o] : 0;
                __syncthreads();
                sh[tid] += t;
                __syncthreads();
            }
            if (i < B) g_off[i + 1] = s_carry + sh[tid];
            __syncthreads();
            if (tid == 0) s_carry += sh[1023];
            __syncthreads();
        }
        Bfinal = B;
    }
    if (tid == 0) g_B = Bfinal;
}

// ---------------------------------------------------------------------------
// Helpers
// ---------------------------------------------------------------------------
__device__ __forceinline__ float4 min4(float4 a, float4 b) {
    return make_float4(fminf(a.x, b.x), fminf(a.y, b.y),
                       fminf(a.z, b.z), fminf(a.w, b.w));
}
__device__ __forceinline__ float4 max4(float4 a, float4 b) {
    return make_float4(fmaxf(a.x, b.x), fmaxf(a.y, b.y),
                       fmaxf(a.z, b.z), fmaxf(a.w, b.w));
}

// ---------------------------------------------------------------------------
// Main kernel: persistent CTAs (2 per SM), each looping over (graph, chunk)
// tiles with grid stride. Per tile (fast path): 8 float4 loads into registers
// (MLP=8), min/max reduced in flight, 2-barrier smem fold publishes mid/inv,
// normalize from registers, streaming stores. Next tile's loads issue right
// behind this tile's stores -> continuous DRAM occupancy. Single DRAM read +
// single DRAM write of the tensor.
// ---------------------------------------------------------------------------
__global__ void __launch_bounds__(NT, 2)
cube_norm_kernel(const float* __restrict__ x, float* __restrict__ y,
                 int ntiles_ub) {
    __shared__ float pmn_s[RB * DC];   // 32 x 60 floats (7680 B)
    __shared__ float pmx_s[RB * DC];   // 7680 B
    __shared__ float smid[DC];
    __shared__ float sinv[DC];

    const int tid = threadIdx.x;
    const int j   = tid % DC4;         // column quad 0..14
    const int rb  = tid / DC4;         // row block 0..31
    const int B   = g_B;

    for (int t = blockIdx.x; t < ntiles_ub; t += gridDim.x) {
        const int g  = t / NCHUNK;
        if (g >= B) break;             // tiles are graph-major; done
        const int c0 = (t - g * NCHUNK) * DC;
        const int r0 = g_off[g];
        const int nr = g_off[g + 1] - r0;
        if (nr <= 0) continue;

        const float* xg = x + (size_t)r0 * D_DIM + c0 + 4 * j;
        float*       yg = y + (size_t)r0 * D_DIM + c0 + 4 * j;

        if (nr == TR) {
            // ---- load 8 rows into registers, reduce in flight ----
            const float* p = xg + (size_t)rb * D_DIM;
            float*       q = yg + (size_t)rb * D_DIM;
            float4 v[KIT];
            #pragma unroll
            for (int k = 0; k < KIT; k++)
                v[k] = __ldcs((const float4*)(p + (size_t)k * RB * D_DIM));

            float4 mn = v[0], mx = v[0];
            #pragma unroll
            for (int k = 1; k < KIT; k++) {
                mn = min4(mn, v[k]);
                mx = max4(mx, v[k]);
            }
            *(float4*)&pmn_s[rb * DC + 4 * j] = mn;
            *(float4*)&pmx_s[rb * DC + 4 * j] = mx;
            __syncthreads();

            // ---- fold: 60 threads, one scalar column each ----
            if (tid < DC) {
                float fmn = pmn_s[tid];
                float fmx = pmx_s[tid];
                #pragma unroll
                for (int r = 1; r < RB; r++) {
                    fmn = fminf(fmn, pmn_s[r * DC + tid]);
                    fmx = fmaxf(fmx, pmx_s[r * DC + tid]);
                }
                smid[tid] = (fmx + fmn) * 0.5f;
                sinv[tid] = 1.0f / fmaxf((fmx - fmn) * 0.5f, EPSV);
            }
            __syncthreads();

            const float4 mid = *(const float4*)&smid[4 * j];
            const float4 inv = *(const float4*)&sinv[4 * j];

            // ---- normalize from registers, streaming stores ----
            #pragma unroll
            for (int k = 0; k < KIT; k++) {
                float4 o;
                o.x = (v[k].x - mid.x) * inv.x;
                o.y = (v[k].y - mid.y) * inv.y;
                o.z = (v[k].z - mid.z) * inv.z;
                o.w = (v[k].w - mid.w) * inv.w;
                __stcs((float4*)(q + (size_t)k * RB * D_DIM), o);
            }
            // no barrier needed: next iteration's partial writes are ordered
            // behind this iteration's barrier-2 for every thread.
        } else {
            // ---------------- generic path (not hit by dataset) ------------
            float4 mn = make_float4( 3.402823466e38f,  3.402823466e38f,
                                     3.402823466e38f,  3.402823466e38f);
            float4 mx = make_float4(-3.402823466e38f, -3.402823466e38f,
                                    -3.402823466e38f, -3.402823466e38f);
            for (int r = rb; r < nr; r += RB) {
                float4 a = *(const float4*)(xg + (size_t)r * D_DIM);
                mn = min4(mn, a);
                mx = max4(mx, a);
            }
            *(float4*)&pmn_s[rb * DC + 4 * j] = mn;
            *(float4*)&pmx_s[rb * DC + 4 * j] = mx;
            __syncthreads();
            if (tid < DC) {
                float fmn = pmn_s[tid];
                float fmx = pmx_s[tid];
                #pragma unroll
                for (int r = 1; r < RB; r++) {
                    fmn = fminf(fmn, pmn_s[r * DC + tid]);
                    fmx = fmaxf(fmx, pmx_s[r * DC + tid]);
                }
                smid[tid] = (fmx + fmn) * 0.5f;
                sinv[tid] = 1.0f / fmaxf((fmx - fmn) * 0.5f, EPSV);
            }
            __syncthreads();
            const float4 mid = *(const float4*)&smid[4 * j];
            const float4 inv = *(const float4*)&sinv[4 * j];
            for (int r = rb; r < nr; r += RB) {
                float4 a = *(const float4*)(xg + (size_t)r * D_DIM);
                float4 o;
                o.x = (a.x - mid.x) * inv.x;
                o.y = (a.y - mid.y) * inv.y;
                o.z = (a.z - mid.z) * inv.z;
                o.w = (a.w - mid.w) * inv.w;
                *(float4*)(yg + (size_t)r * D_DIM) = o;
            }
            __syncthreads();   // generic path: protect smem across iterations
        }
    }
}

// ---------------------------------------------------------------------------
extern "C" void kernel_launch(void* const* d_in, const int* in_sizes, int n_in,
                              void* d_out, int out_size) {
    const float* x  = (const float*)d_in[0];
    const int*   bl = (const int*)d_in[1];
    float*       y  = (float*)d_out;

    const int nb   = in_sizes[1];
    const int ntot = in_sizes[0] / D_DIM;

    offsets_kernel<<<1, 1024>>>(bl, nb, ntot);

    int nbc = nb < MAXB ? nb : MAXB;
    if (nbc < 1) nbc = 1;
    const int ntiles_ub = NCHUNK * nbc;   // upper bound; kernel stops at g_B

    int sms = 148;
    cudaDeviceGetAttribute(&sms, cudaDevAttrMultiProcessorCount, 0);
    int grid = 2 * sms;                   // persistent: 2 CTAs per SM
    if (grid > ntiles_ub) grid = ntiles_ub;

    cube_norm_kernel<<<grid, NT>>>(x, y, ntiles_ub);
}